// round 1
// baseline (speedup 1.0000x reference)
#include <cuda_runtime.h>
#include <math.h>

// ---------------------------------------------------------------------------
// PatchedAttentionTransformerDecoderLayer
//   B=16, T=64 patches, P=256, DM=1024, H=16, HD=64, S=2048, DFF=1024
// Pipeline:
//   KV = src @ [Wk|Wv] + [bk|bv]            (two 32768x1024x1024 GEMMs)
//   Q  = tgt @ Wq + bq                      (1024x1024x256)
//   A  = softmax(Q K^T / 8) V               (flash attention per (b,h))
//   X1 = LN(A @ Wo + bo + tgt)
//   F  = relu(X1 @ W1 + bf1) @ W2 + bf2
//   out = LN(F + X1)
// ---------------------------------------------------------------------------

// Scratch (device globals; no runtime allocation allowed)
__device__ float g_KV[(size_t)32768 * 2048];   // [B*S, 2048]: cols 0..1023 = K, 1024..2047 = V
__device__ float g_Q [(size_t)1024 * 1024];    // [B*T, DM]
__device__ float g_A [(size_t)1024 * 1024];    // attention output [B*T, DM]
__device__ float g_F1[(size_t)1024 * 1024];    // FFN hidden [B*T, DFF]
__device__ float g_T1[(size_t)1024 * 256];     // pre-LN temp [B*T, P]
__device__ float g_X1[(size_t)1024 * 256];     // post-LN1 [B*T, P]

// ---------------------------------------------------------------------------
// Generic tiled fp32 GEMM: C[M,N] = A[M,K] @ B[K,N] + bias  (optional ReLU)
// BM=BN=64, BK=16, 256 threads, 4x4 register tile per thread.
// grid = (N/64, M/64)
// ---------------------------------------------------------------------------
template<bool RELU>
__global__ __launch_bounds__(256) void gemm64x64(
    const float* __restrict__ A, int lda,
    const float* __restrict__ B, int ldb,
    const float* __restrict__ bias,
    float* __restrict__ C, int ldc, int K)
{
    __shared__ float As[16][64];   // transposed: As[k][m]
    __shared__ float Bs[16][64];   // Bs[k][n]

    const int tid = threadIdx.x;
    const int tx = tid & 15;       // output col group
    const int ty = tid >> 4;       // output row group
    const int r0 = blockIdx.y * 64;
    const int c0 = blockIdx.x * 64;

    float acc[4][4];
#pragma unroll
    for (int i = 0; i < 4; i++)
#pragma unroll
        for (int j = 0; j < 4; j++) acc[i][j] = 0.f;

    const int arow = tid >> 2;           // 0..63
    const int ak   = (tid & 3) * 4;      // 0,4,8,12
    const int bk   = tid >> 4;           // 0..15
    const int bj   = (tid & 15) * 4;     // 0..60

    const float* Ap = A + (size_t)(r0 + arow) * lda + ak;
    const float* Bp = B + (size_t)bk * ldb + c0 + bj;

    for (int kb = 0; kb < K; kb += 16) {
        float4 a4 = *(const float4*)(Ap + kb);
        As[ak + 0][arow] = a4.x;
        As[ak + 1][arow] = a4.y;
        As[ak + 2][arow] = a4.z;
        As[ak + 3][arow] = a4.w;
        *(float4*)&Bs[bk][bj] = *(const float4*)(Bp + (size_t)kb * ldb);
        __syncthreads();

#pragma unroll
        for (int k = 0; k < 16; k++) {
            float4 ra4 = *(const float4*)&As[k][ty * 4];
            float4 rb4 = *(const float4*)&Bs[k][tx * 4];
            float ra[4] = {ra4.x, ra4.y, ra4.z, ra4.w};
            float rb[4] = {rb4.x, rb4.y, rb4.z, rb4.w};
#pragma unroll
            for (int i = 0; i < 4; i++)
#pragma unroll
                for (int j = 0; j < 4; j++)
                    acc[i][j] = fmaf(ra[i], rb[j], acc[i][j]);
        }
        __syncthreads();
    }

#pragma unroll
    for (int i = 0; i < 4; i++) {
        float* Cp = C + (size_t)(r0 + ty * 4 + i) * ldc + c0 + tx * 4;
#pragma unroll
        for (int j = 0; j < 4; j++) {
            float v = acc[i][j] + bias[c0 + tx * 4 + j];
            if (RELU) v = fmaxf(v, 0.f);
            Cp[j] = v;
        }
    }
}

// ---------------------------------------------------------------------------
// Flash attention, one block per (b,h). 256 threads.
// Q tile [64 x 64] in smem (pre-scaled by 1/8), iterate S=2048 in 32-key chunks
// with online softmax. Thread (ty,tx): queries t = ty+16*i (i<4),
// chunk keys s = tx+16*j (j<2), output cols d = tx*4+jj (jj<4).
// ---------------------------------------------------------------------------
__global__ __launch_bounds__(256) void attn_kernel(
    const float* __restrict__ Q,
    const float* __restrict__ KV,
    float* __restrict__ Aout)
{
    __shared__ float Qs[64][64];
    __shared__ float Ks[32][65];   // padded: conflict-free K[s][d] column reads
    __shared__ float Vs[32][64];
    __shared__ float Ss[64][33];   // softmax probs p[t][s]

    const int bh = blockIdx.x;
    const int b = bh >> 4, h = bh & 15;
    const float* Qb = Q  + (size_t)b * 64 * 1024 + h * 64;
    const float* Kb = KV + (size_t)b * 2048 * 2048 + h * 64;
    const float* Vb = Kb + 1024;

    const int tid = threadIdx.x;
    const int tx = tid & 15, ty = tid >> 4;

    for (int f = tid; f < 4096; f += 256) {
        int t = f >> 6, d = f & 63;
        Qs[t][d] = Qb[(size_t)t * 1024 + d] * 0.125f;   // fold in 1/sqrt(64)
    }

    float out[4][4];
    float m[4], l[4];
#pragma unroll
    for (int i = 0; i < 4; i++) {
        m[i] = -1e30f; l[i] = 0.f;
#pragma unroll
        for (int j = 0; j < 4; j++) out[i][j] = 0.f;
    }
    __syncthreads();

    for (int s0 = 0; s0 < 2048; s0 += 32) {
        for (int f = tid; f < 2048; f += 256) {
            int s = f >> 6, d = f & 63;
            size_t g = (size_t)(s0 + s) * 2048 + d;
            Ks[s][d] = Kb[g];
            Vs[s][d] = Vb[g];
        }
        __syncthreads();

        // scores r[i][j] = q_t . k_s
        float r[4][2];
#pragma unroll
        for (int i = 0; i < 4; i++) { r[i][0] = 0.f; r[i][1] = 0.f; }
#pragma unroll 8
        for (int d = 0; d < 64; d++) {
            float k0 = Ks[tx][d];
            float k1 = Ks[tx + 16][d];
#pragma unroll
            for (int i = 0; i < 4; i++) {
                float q = Qs[ty + 16 * i][d];
                r[i][0] = fmaf(q, k0, r[i][0]);
                r[i][1] = fmaf(q, k1, r[i][1]);
            }
        }

        // online softmax update per query row
#pragma unroll
        for (int i = 0; i < 4; i++) {
            int t = ty + 16 * i;
            float cm = fmaxf(r[i][0], r[i][1]);
#pragma unroll
            for (int off = 8; off > 0; off >>= 1)
                cm = fmaxf(cm, __shfl_xor_sync(0xffffffffu, cm, off, 16));
            float mn = fmaxf(m[i], cm);
            float f_old = __expf(m[i] - mn);
            float p0 = __expf(r[i][0] - mn);
            float p1 = __expf(r[i][1] - mn);
            Ss[t][tx]      = p0;
            Ss[t][tx + 16] = p1;
            float cs = p0 + p1;
#pragma unroll
            for (int off = 8; off > 0; off >>= 1)
                cs += __shfl_xor_sync(0xffffffffu, cs, off, 16);
            l[i] = l[i] * f_old + cs;
            m[i] = mn;
#pragma unroll
            for (int j = 0; j < 4; j++) out[i][j] *= f_old;
        }
        __syncthreads();

        // out[t][d] += sum_s p[t][s] * V[s][d]
#pragma unroll 4
        for (int s = 0; s < 32; s++) {
            float4 v = *(const float4*)&Vs[s][tx * 4];
#pragma unroll
            for (int i = 0; i < 4; i++) {
                float p = Ss[ty + 16 * i][s];
                out[i][0] = fmaf(p, v.x, out[i][0]);
                out[i][1] = fmaf(p, v.y, out[i][1]);
                out[i][2] = fmaf(p, v.z, out[i][2]);
                out[i][3] = fmaf(p, v.w, out[i][3]);
            }
        }
        __syncthreads();
    }

#pragma unroll
    for (int i = 0; i < 4; i++) {
        int t = ty + 16 * i;
        float inv = 1.f / l[i];
        float* Ap = Aout + (size_t)(b * 64 + t) * 1024 + h * 64 + tx * 4;
#pragma unroll
        for (int j = 0; j < 4; j++) Ap[j] = out[i][j] * inv;
    }
}

// ---------------------------------------------------------------------------
// out[row] = LayerNorm(pre[row] + res[row]) * g + b    (row length 256)
// one block (256 threads) per row
// ---------------------------------------------------------------------------
__global__ __launch_bounds__(256) void add_ln_kernel(
    const float* __restrict__ pre,
    const float* __restrict__ res,
    const float* __restrict__ g,
    const float* __restrict__ bta,
    float* __restrict__ out)
{
    const int row = blockIdx.x;
    const int t = threadIdx.x;
    const size_t idx = (size_t)row * 256 + t;

    float v = pre[idx] + res[idx];
    float s = v, s2 = v * v;
#pragma unroll
    for (int off = 16; off > 0; off >>= 1) {
        s  += __shfl_xor_sync(0xffffffffu, s,  off);
        s2 += __shfl_xor_sync(0xffffffffu, s2, off);
    }
    __shared__ float rs[8], rs2[8];
    const int w = t >> 5, lane = t & 31;
    if (lane == 0) { rs[w] = s; rs2[w] = s2; }
    __syncthreads();
    if (t < 32) {
        s  = (t < 8) ? rs[t]  : 0.f;
        s2 = (t < 8) ? rs2[t] : 0.f;
#pragma unroll
        for (int off = 4; off > 0; off >>= 1) {
            s  += __shfl_xor_sync(0xffffffffu, s,  off);
            s2 += __shfl_xor_sync(0xffffffffu, s2, off);
        }
        if (t == 0) { rs[0] = s; rs2[0] = s2; }
    }
    __syncthreads();
    float mean = rs[0] * (1.f / 256.f);
    float var  = rs2[0] * (1.f / 256.f) - mean * mean;
    out[idx] = (v - mean) * rsqrtf(var + 1e-5f) * g[t] + bta[t];
}

// ---------------------------------------------------------------------------
extern "C" void kernel_launch(void* const* d_in, const int* in_sizes, int n_in,
                              void* d_out, int out_size)
{
    const float* src  = (const float*)d_in[0];   // [16,2048,1024]
    const float* tgt  = (const float*)d_in[1];   // [16,16384] == [1024,256]
    const float* Wq   = (const float*)d_in[2];   // [256,1024]
    const float* bq   = (const float*)d_in[3];
    const float* Wk   = (const float*)d_in[4];   // [1024,1024]
    const float* bk   = (const float*)d_in[5];
    const float* Wv   = (const float*)d_in[6];   // [1024,1024]
    const float* bv   = (const float*)d_in[7];
    const float* Wo   = (const float*)d_in[8];   // [1024,256]
    const float* bo   = (const float*)d_in[9];
    const float* ln1g = (const float*)d_in[10];
    const float* ln1b = (const float*)d_in[11];
    const float* W1   = (const float*)d_in[12];  // [256,1024]
    const float* bf1  = (const float*)d_in[13];
    const float* W2   = (const float*)d_in[14];  // [1024,256]
    const float* bf2  = (const float*)d_in[15];
    const float* ln3g = (const float*)d_in[16];
    const float* ln3b = (const float*)d_in[17];
    float* out = (float*)d_out;

    float *KV, *Qp, *Ap, *F1, *T1, *X1;
    cudaGetSymbolAddress((void**)&KV, g_KV);
    cudaGetSymbolAddress((void**)&Qp, g_Q);
    cudaGetSymbolAddress((void**)&Ap, g_A);
    cudaGetSymbolAddress((void**)&F1, g_F1);
    cudaGetSymbolAddress((void**)&T1, g_T1);
    cudaGetSymbolAddress((void**)&X1, g_X1);

    const dim3 blk(256);

    // K and V projections: [32768,1024] @ [1024,1024]  (dominant cost)
    gemm64x64<false><<<dim3(16, 512), blk>>>(src, 1024, Wk, 1024, bk, KV,        2048, 1024);
    gemm64x64<false><<<dim3(16, 512), blk>>>(src, 1024, Wv, 1024, bv, KV + 1024, 2048, 1024);

    // Q projection: [1024,256] @ [256,1024]
    gemm64x64<false><<<dim3(16, 16), blk>>>(tgt, 256, Wq, 1024, bq, Qp, 1024, 256);

    // attention: one block per (b,h)
    attn_kernel<<<256, blk>>>(Qp, KV, Ap);

    // output projection + residual + LN1
    gemm64x64<false><<<dim3(4, 16), blk>>>(Ap, 1024, Wo, 256, bo, T1, 256, 1024);
    add_ln_kernel<<<1024, 256>>>(T1, tgt, ln1g, ln1b, X1);

    // FFN
    gemm64x64<true ><<<dim3(16, 16), blk>>>(X1, 256, W1, 1024, bf1, F1, 1024, 256);
    gemm64x64<false><<<dim3(4, 16), blk>>>(F1, 1024, W2, 256, bf2, T1, 256, 1024);

    // residual + LN3 -> output
    add_ln_kernel<<<1024, 256>>>(T1, X1, ln3g, ln3b, out);
}

// round 3
// speedup vs baseline: 2.2561x; 2.2561x over previous
#include <cuda_runtime.h>
#include <cuda_bf16.h>
#include <math.h>
#include <stdint.h>

// ---------------------------------------------------------------------------
// PatchedAttentionTransformerDecoderLayer — Round 2 resubmit (infra failure):
//   All dense GEMMs via mma.sync.m16n8k16 bf16 with hi/lo split (3 MMAs),
//   fp32 accumulate -> near-fp32 precision on the tensor pipe.
// ---------------------------------------------------------------------------

__device__ float g_KV[(size_t)32768 * 2048];   // [B*S, 2048]: K | V
__device__ float g_Q [(size_t)1024 * 1024];
__device__ float g_A [(size_t)1024 * 1024];
__device__ float g_F1[(size_t)1024 * 1024];
__device__ float g_T1[(size_t)1024 * 256];
__device__ float g_X1[(size_t)1024 * 256];

// split fp32 pair into packed bf16 hi and lo (residual) pairs
__device__ __forceinline__ void split2(float x0, float x1, uint32_t& hi, uint32_t& lo) {
    __nv_bfloat16 h0 = __float2bfloat16(x0), h1 = __float2bfloat16(x1);
    float r0 = x0 - __bfloat162float(h0);
    float r1 = x1 - __bfloat162float(h1);
    __nv_bfloat16 l0 = __float2bfloat16(r0), l1 = __float2bfloat16(r1);
    hi = (uint32_t)__bfloat16_as_ushort(h0) | ((uint32_t)__bfloat16_as_ushort(h1) << 16);
    lo = (uint32_t)__bfloat16_as_ushort(l0) | ((uint32_t)__bfloat16_as_ushort(l1) << 16);
}

__device__ __forceinline__ void mma16816(float* c, const uint32_t* a, uint32_t b0, uint32_t b1) {
    asm volatile(
        "mma.sync.aligned.m16n8k16.row.col.f32.bf16.bf16.f32 "
        "{%0,%1,%2,%3}, {%4,%5,%6,%7}, {%8,%9}, {%0,%1,%2,%3};"
        : "+f"(c[0]), "+f"(c[1]), "+f"(c[2]), "+f"(c[3])
        : "r"(a[0]), "r"(a[1]), "r"(a[2]), "r"(a[3]), "r"(b0), "r"(b1));
}

// ---------------------------------------------------------------------------
// C[M,N] = A[M,K] @ W[K,N] + bias, optional ReLU.  fp32 in/out.
// Block tile 128x128, BK=32, 256 threads = 8 warps (4 m-warps x 2 n-warps),
// warp tile 32x64. bf16 hi/lo x3 MMA emulation.
// grid = (N/128, M/128); requires M%128==0, N%128==0, K%32==0.
// ---------------------------------------------------------------------------
#define A_PITCH 40    // halves per row (32 + 8 pad)
#define B_PITCH 136   // halves per row (128 + 8 pad)

template<bool RELU>
__global__ __launch_bounds__(256) void gemm_tc(
    const float* __restrict__ A, int lda,
    const float* __restrict__ W, int ldb,
    const float* __restrict__ bias,
    float* __restrict__ C, int ldc, int K)
{
    __shared__ unsigned short AsH[128 * A_PITCH];
    __shared__ unsigned short AsL[128 * A_PITCH];
    __shared__ unsigned short BsH[32 * B_PITCH];
    __shared__ unsigned short BsL[32 * B_PITCH];

    const int tid  = threadIdx.x;
    const int lane = tid & 31;
    const int wid  = tid >> 5;
    const int wm   = wid & 3;          // 0..3  (m)
    const int wn   = wid >> 2;         // 0..1  (n)
    const int g    = lane >> 2;        // groupID 0..7
    const int tig  = lane & 3;         // 0..3

    const int r0 = blockIdx.y * 128;
    const int c0 = blockIdx.x * 128;

    float acc[2][8][4];
#pragma unroll
    for (int mt = 0; mt < 2; mt++)
#pragma unroll
        for (int nt = 0; nt < 8; nt++)
#pragma unroll
            for (int j = 0; j < 4; j++) acc[mt][nt][j] = 0.f;

    for (int kb = 0; kb < K; kb += 32) {
        // ---- load A tile 128x32 (fp32 -> bf16 hi/lo) ----
#pragma unroll
        for (int i = 0; i < 4; i++) {
            int flat = tid + 256 * i;            // 0..1023 float4s
            int row = flat >> 3;
            int kc  = (flat & 7) * 4;
            float4 a4 = *(const float4*)(A + (size_t)(r0 + row) * lda + kb + kc);
            uint32_t hi, lo;
            split2(a4.x, a4.y, hi, lo);
            *(uint32_t*)&AsH[row * A_PITCH + kc] = hi;
            *(uint32_t*)&AsL[row * A_PITCH + kc] = lo;
            split2(a4.z, a4.w, hi, lo);
            *(uint32_t*)&AsH[row * A_PITCH + kc + 2] = hi;
            *(uint32_t*)&AsL[row * A_PITCH + kc + 2] = lo;
        }
        // ---- load B tile 32x128 ----
#pragma unroll
        for (int i = 0; i < 4; i++) {
            int flat = tid + 256 * i;
            int kr = flat >> 5;
            int nc = (flat & 31) * 4;
            float4 b4 = *(const float4*)(W + (size_t)(kb + kr) * ldb + c0 + nc);
            uint32_t hi, lo;
            split2(b4.x, b4.y, hi, lo);
            *(uint32_t*)&BsH[kr * B_PITCH + nc] = hi;
            *(uint32_t*)&BsL[kr * B_PITCH + nc] = lo;
            split2(b4.z, b4.w, hi, lo);
            *(uint32_t*)&BsH[kr * B_PITCH + nc + 2] = hi;
            *(uint32_t*)&BsL[kr * B_PITCH + nc + 2] = lo;
        }
        __syncthreads();

#pragma unroll
        for (int ks = 0; ks < 32; ks += 16) {
            uint32_t aH[2][4], aL[2][4];
#pragma unroll
            for (int mt = 0; mt < 2; mt++) {
                int rA = wm * 32 + mt * 16 + g;
                int cA = ks + tig * 2;
                aH[mt][0] = *(const uint32_t*)&AsH[rA * A_PITCH + cA];
                aH[mt][1] = *(const uint32_t*)&AsH[(rA + 8) * A_PITCH + cA];
                aH[mt][2] = *(const uint32_t*)&AsH[rA * A_PITCH + cA + 8];
                aH[mt][3] = *(const uint32_t*)&AsH[(rA + 8) * A_PITCH + cA + 8];
                aL[mt][0] = *(const uint32_t*)&AsL[rA * A_PITCH + cA];
                aL[mt][1] = *(const uint32_t*)&AsL[(rA + 8) * A_PITCH + cA];
                aL[mt][2] = *(const uint32_t*)&AsL[rA * A_PITCH + cA + 8];
                aL[mt][3] = *(const uint32_t*)&AsL[(rA + 8) * A_PITCH + cA + 8];
            }
#pragma unroll
            for (int nt = 0; nt < 8; nt++) {
                int col = wn * 64 + nt * 8 + g;
                int rb  = (ks + tig * 2) * B_PITCH + col;
                uint32_t bH0 = (uint32_t)BsH[rb] | ((uint32_t)BsH[rb + B_PITCH] << 16);
                uint32_t bL0 = (uint32_t)BsL[rb] | ((uint32_t)BsL[rb + B_PITCH] << 16);
                int rb8 = rb + 8 * B_PITCH;
                uint32_t bH1 = (uint32_t)BsH[rb8] | ((uint32_t)BsH[rb8 + B_PITCH] << 16);
                uint32_t bL1 = (uint32_t)BsL[rb8] | ((uint32_t)BsL[rb8 + B_PITCH] << 16);
#pragma unroll
                for (int mt = 0; mt < 2; mt++) {
                    mma16816(acc[mt][nt], aH[mt], bH0, bH1);
                    mma16816(acc[mt][nt], aH[mt], bL0, bL1);
                    mma16816(acc[mt][nt], aL[mt], bH0, bH1);
                }
            }
        }
        __syncthreads();
    }

    // ---- epilogue: bias (+ReLU), fp32 stores ----
#pragma unroll
    for (int mt = 0; mt < 2; mt++) {
        int r = r0 + wm * 32 + mt * 16 + g;
#pragma unroll
        for (int nt = 0; nt < 8; nt++) {
            int col = c0 + wn * 64 + nt * 8 + tig * 2;
            float b0 = bias[col], b1 = bias[col + 1];
            float v0 = acc[mt][nt][0] + b0;
            float v1 = acc[mt][nt][1] + b1;
            float v2 = acc[mt][nt][2] + b0;
            float v3 = acc[mt][nt][3] + b1;
            if (RELU) {
                v0 = fmaxf(v0, 0.f); v1 = fmaxf(v1, 0.f);
                v2 = fmaxf(v2, 0.f); v3 = fmaxf(v3, 0.f);
            }
            *(float2*)(C + (size_t)r * ldc + col)       = make_float2(v0, v1);
            *(float2*)(C + (size_t)(r + 8) * ldc + col) = make_float2(v2, v3);
        }
    }
}

// ---------------------------------------------------------------------------
// Flash attention, one block per (b,h). 256 threads.
// ---------------------------------------------------------------------------
__global__ __launch_bounds__(256) void attn_kernel(
    const float* __restrict__ Q,
    const float* __restrict__ KV,
    float* __restrict__ Aout)
{
    __shared__ float Qs[64][64];
    __shared__ float Ks[32][65];
    __shared__ float Vs[32][64];
    __shared__ float Ss[64][33];

    const int bh = blockIdx.x;
    const int b = bh >> 4, h = bh & 15;
    const float* Qb = Q  + (size_t)b * 64 * 1024 + h * 64;
    const float* Kb = KV + (size_t)b * 2048 * 2048 + h * 64;
    const float* Vb = Kb + 1024;

    const int tid = threadIdx.x;
    const int tx = tid & 15, ty = tid >> 4;

    for (int f = tid; f < 4096; f += 256) {
        int t = f >> 6, d = f & 63;
        Qs[t][d] = Qb[(size_t)t * 1024 + d] * 0.125f;
    }

    float out[4][4];
    float m[4], l[4];
#pragma unroll
    for (int i = 0; i < 4; i++) {
        m[i] = -1e30f; l[i] = 0.f;
#pragma unroll
        for (int j = 0; j < 4; j++) out[i][j] = 0.f;
    }
    __syncthreads();

    for (int s0 = 0; s0 < 2048; s0 += 32) {
        for (int f = tid; f < 2048; f += 256) {
            int s = f >> 6, d = f & 63;
            size_t gidx = (size_t)(s0 + s) * 2048 + d;
            Ks[s][d] = Kb[gidx];
            Vs[s][d] = Vb[gidx];
        }
        __syncthreads();

        float r[4][2];
#pragma unroll
        for (int i = 0; i < 4; i++) { r[i][0] = 0.f; r[i][1] = 0.f; }
#pragma unroll 8
        for (int d = 0; d < 64; d++) {
            float k0 = Ks[tx][d];
            float k1 = Ks[tx + 16][d];
#pragma unroll
            for (int i = 0; i < 4; i++) {
                float q = Qs[ty + 16 * i][d];
                r[i][0] = fmaf(q, k0, r[i][0]);
                r[i][1] = fmaf(q, k1, r[i][1]);
            }
        }

#pragma unroll
        for (int i = 0; i < 4; i++) {
            int t = ty + 16 * i;
            float cm = fmaxf(r[i][0], r[i][1]);
#pragma unroll
            for (int off = 8; off > 0; off >>= 1)
                cm = fmaxf(cm, __shfl_xor_sync(0xffffffffu, cm, off, 16));
            float mn = fmaxf(m[i], cm);
            float f_old = __expf(m[i] - mn);
            float p0 = __expf(r[i][0] - mn);
            float p1 = __expf(r[i][1] - mn);
            Ss[t][tx]      = p0;
            Ss[t][tx + 16] = p1;
            float cs = p0 + p1;
#pragma unroll
            for (int off = 8; off > 0; off >>= 1)
                cs += __shfl_xor_sync(0xffffffffu, cs, off, 16);
            l[i] = l[i] * f_old + cs;
            m[i] = mn;
#pragma unroll
            for (int j = 0; j < 4; j++) out[i][j] *= f_old;
        }
        __syncthreads();

#pragma unroll 4
        for (int s = 0; s < 32; s++) {
            float4 v = *(const float4*)&Vs[s][tx * 4];
#pragma unroll
            for (int i = 0; i < 4; i++) {
                float p = Ss[ty + 16 * i][s];
                out[i][0] = fmaf(p, v.x, out[i][0]);
                out[i][1] = fmaf(p, v.y, out[i][1]);
                out[i][2] = fmaf(p, v.z, out[i][2]);
                out[i][3] = fmaf(p, v.w, out[i][3]);
            }
        }
        __syncthreads();
    }

#pragma unroll
    for (int i = 0; i < 4; i++) {
        int t = ty + 16 * i;
        float inv = 1.f / l[i];
        float* Ap = Aout + (size_t)(b * 64 + t) * 1024 + h * 64 + tx * 4;
#pragma unroll
        for (int j = 0; j < 4; j++) Ap[j] = out[i][j] * inv;
    }
}

// ---------------------------------------------------------------------------
// out[row] = LayerNorm(pre[row] + res[row]) * g + b   (row length 256)
// ---------------------------------------------------------------------------
__global__ __launch_bounds__(256) void add_ln_kernel(
    const float* __restrict__ pre,
    const float* __restrict__ res,
    const float* __restrict__ g,
    const float* __restrict__ bta,
    float* __restrict__ out)
{
    const int row = blockIdx.x;
    const int t = threadIdx.x;
    const size_t idx = (size_t)row * 256 + t;

    float v = pre[idx] + res[idx];
    float s = v, s2 = v * v;
#pragma unroll
    for (int off = 16; off > 0; off >>= 1) {
        s  += __shfl_xor_sync(0xffffffffu, s,  off);
        s2 += __shfl_xor_sync(0xffffffffu, s2, off);
    }
    __shared__ float rs[8], rs2[8];
    const int w = t >> 5, lane = t & 31;
    if (lane == 0) { rs[w] = s; rs2[w] = s2; }
    __syncthreads();
    if (t < 32) {
        s  = (t < 8) ? rs[t]  : 0.f;
        s2 = (t < 8) ? rs2[t] : 0.f;
#pragma unroll
        for (int off = 4; off > 0; off >>= 1) {
            s  += __shfl_xor_sync(0xffffffffu, s,  off);
            s2 += __shfl_xor_sync(0xffffffffu, s2, off);
        }
        if (t == 0) { rs[0] = s; rs2[0] = s2; }
    }
    __syncthreads();
    float mean = rs[0] * (1.f / 256.f);
    float var  = rs2[0] * (1.f / 256.f) - mean * mean;
    out[idx] = (v - mean) * rsqrtf(var + 1e-5f) * g[t] + bta[t];
}

// ---------------------------------------------------------------------------
extern "C" void kernel_launch(void* const* d_in, const int* in_sizes, int n_in,
                              void* d_out, int out_size)
{
    const float* src  = (const float*)d_in[0];
    const float* tgt  = (const float*)d_in[1];
    const float* Wq   = (const float*)d_in[2];
    const float* bq   = (const float*)d_in[3];
    const float* Wk   = (const float*)d_in[4];
    const float* bk   = (const float*)d_in[5];
    const float* Wv   = (const float*)d_in[6];
    const float* bv   = (const float*)d_in[7];
    const float* Wo   = (const float*)d_in[8];
    const float* bo   = (const float*)d_in[9];
    const float* ln1g = (const float*)d_in[10];
    const float* ln1b = (const float*)d_in[11];
    const float* W1   = (const float*)d_in[12];
    const float* bf1  = (const float*)d_in[13];
    const float* W2   = (const float*)d_in[14];
    const float* bf2  = (const float*)d_in[15];
    const float* ln3g = (const float*)d_in[16];
    const float* ln3b = (const float*)d_in[17];
    float* out = (float*)d_out;

    float *KV, *Qp, *Ap, *F1, *T1, *X1;
    cudaGetSymbolAddress((void**)&KV, g_KV);
    cudaGetSymbolAddress((void**)&Qp, g_Q);
    cudaGetSymbolAddress((void**)&Ap, g_A);
    cudaGetSymbolAddress((void**)&F1, g_F1);
    cudaGetSymbolAddress((void**)&T1, g_T1);
    cudaGetSymbolAddress((void**)&X1, g_X1);

    const dim3 blk(256);

    // K and V projections: [32768,1024] @ [1024,1024]  (dominant)
    gemm_tc<false><<<dim3(8, 256), blk>>>(src, 1024, Wk, 1024, bk, KV,        2048, 1024);
    gemm_tc<false><<<dim3(8, 256), blk>>>(src, 1024, Wv, 1024, bv, KV + 1024, 2048, 1024);

    // Q projection: [1024,256] @ [256,1024]
    gemm_tc<false><<<dim3(8, 8), blk>>>(tgt, 256, Wq, 1024, bq, Qp, 1024, 256);

    // attention
    attn_kernel<<<256, blk>>>(Qp, KV, Ap);

    // output projection + residual + LN1
    gemm_tc<false><<<dim3(2, 8), blk>>>(Ap, 1024, Wo, 256, bo, T1, 256, 1024);
    add_ln_kernel<<<1024, 256>>>(T1, tgt, ln1g, ln1b, X1);

    // FFN
    gemm_tc<true ><<<dim3(8, 8), blk>>>(X1, 256, W1, 1024, bf1, F1, 1024, 256);
    gemm_tc<false><<<dim3(2, 8), blk>>>(F1, 1024, W2, 256, bf2, T1, 256, 1024);

    // residual + LN3 -> output
    add_ln_kernel<<<1024, 256>>>(T1, X1, ln3g, ln3b, out);
}